// round 10
// baseline (speedup 1.0000x reference)
#include <cuda_runtime.h>
#include <cuda_fp16.h>
#include <cstdint>

#define G_DATA  262144
#define G_TRUNC 40000
#define NEDGE   1048576
#define FEAT    128
#define EPSV    1e-8f

#define NBLK_DOWN 40     // ceil(G_TRUNC/1024)
#define NBLK_UP   256    // G_DATA/1024

// ---------------- scratch (__device__ globals; no allocation allowed) --------
// INVARIANT: g_cnt_* are zero at entry to kernel_launch. They start zero
// (static init) and the countdown scatter returns them to zero every call.
__device__ __half g_xh[(size_t)G_DATA * FEAT];        // 67 MB fp16 copy of x slice
__device__ __half g_xc[(size_t)G_TRUNC * FEAT];       // 10.2 MB fp16 intermediate
__device__ int   g_cnt_down[G_TRUNC];
__device__ int   g_cnt_up[G_DATA];
__device__ int   g_off_down[G_TRUNC + 1];
__device__ int   g_off_up[G_DATA + 1];
__device__ int   g_bsum_down[NBLK_DOWN];
__device__ int   g_bsum_up[NBLK_UP];
__device__ int2  g_edges_down[NEDGE];                 // (src, w bits) bucketed by dst
__device__ int2  g_edges_up[NEDGE];

// ---------------- hist + fp32->fp16 convert (fused) --------------------------
// hist is spread-atomic bound with near-zero data traffic; the convert DRAM
// stream overlaps it well (unlike scatter, which is itself LTS-heavy).
// Grid: NEDGE/4 threads. Each thread: 4+4 histogram atomics (int4 reads) and
// 32 streaming float4->half4 conversions (NEDGE/4 * 32 == G_DATA*FEAT/4).
__global__ void __launch_bounds__(256) hist_convert_kernel(
    const int* __restrict__ ddst, const int* __restrict__ udst,
    const float* __restrict__ x)
{
    int i = blockIdx.x * blockDim.x + threadIdx.x;     // 0 .. NEDGE/4-1
    int4 dd = __ldg(&reinterpret_cast<const int4*>(ddst)[i]);
    int4 ud = __ldg(&reinterpret_cast<const int4*>(udst)[i]);
    atomicAdd(&g_cnt_down[dd.x], 1);
    atomicAdd(&g_cnt_down[dd.y], 1);
    atomicAdd(&g_cnt_down[dd.z], 1);
    atomicAdd(&g_cnt_down[dd.w], 1);
    atomicAdd(&g_cnt_up[ud.x], 1);
    atomicAdd(&g_cnt_up[ud.y], 1);
    atomicAdd(&g_cnt_up[ud.z], 1);
    atomicAdd(&g_cnt_up[ud.w], 1);

    const float4* x4 = reinterpret_cast<const float4*>(x);
    uint2* xh2 = reinterpret_cast<uint2*>(g_xh);
    const int NT = NEDGE / 4;                          // 262144 threads
#pragma unroll 4
    for (int k = 0; k < 32; k++) {                     // 32*NT == G_DATA*FEAT/4
        int j = i + k * NT;
        float4 v = __ldcs(&x4[j]);
        __half2 h01 = __floats2half2_rn(v.x, v.y);
        __half2 h23 = __floats2half2_rn(v.z, v.w);
        xh2[j] = make_uint2(*reinterpret_cast<unsigned*>(&h01),
                            *reinterpret_cast<unsigned*>(&h23));
    }
}

// ---------------- scans ------------------------------------------------------

// Per-1024-chunk sums for both arrays in one launch (blocks [0,40)=down).
__global__ void scan_partial_both() {
    __shared__ int red[256];
    int blk = blockIdx.x;
    const int* cnt; int* bsum; int n; int b;
    if (blk < NBLK_DOWN) { cnt = g_cnt_down; bsum = g_bsum_down; n = G_TRUNC; b = blk; }
    else                 { cnt = g_cnt_up;   bsum = g_bsum_up;   n = G_DATA;  b = blk - NBLK_DOWN; }
    int base = b * 1024 + threadIdx.x * 4;
    int s = 0;
#pragma unroll
    for (int j = 0; j < 4; j++) { int i = base + j; if (i < n) s += cnt[i]; }
    red[threadIdx.x] = s;
    __syncthreads();
    for (int off = 128; off > 0; off >>= 1) {
        if (threadIdx.x < off) red[threadIdx.x] += red[threadIdx.x + off];
        __syncthreads();
    }
    if (threadIdx.x == 0) bsum[b] = red[0];
}

// Per-element exclusive scan. Each block redundantly scans the (<=256) block
// sums itself. cnt is left intact (the scatter's countdown cursor consumes it).
__global__ void scan_final_both() {
    int blk = blockIdx.x;
    const int* cnt; int* off; const int* bsum; int n, nblk, b;
    if (blk < NBLK_DOWN) { cnt = g_cnt_down; off = g_off_down; bsum = g_bsum_down;
                           n = G_TRUNC; nblk = NBLK_DOWN; b = blk; }
    else                 { cnt = g_cnt_up;   off = g_off_up;   bsum = g_bsum_up;
                           n = G_DATA;  nblk = NBLK_UP;   b = blk - NBLK_DOWN; }
    int t = threadIdx.x;
    int lane = t & 31, wid = t >> 5;

    __shared__ int s[256];
    int bv = (t < nblk) ? bsum[t] : 0;
    s[t] = bv;
    __syncthreads();
    for (int o = 1; o < 256; o <<= 1) {
        int add = (t >= o) ? s[t - o] : 0;
        __syncthreads();
        s[t] += add;
        __syncthreads();
    }
    int block_off = (b > 0) ? s[b - 1] : 0;
    if (b == 0 && t == 0) off[n] = s[nblk - 1];   // grand total

    int base = b * 1024 + t * 4;
    int v0 = 0, v1 = 0, v2 = 0, v3 = 0;
    if (base + 0 < n) v0 = cnt[base + 0];
    if (base + 1 < n) v1 = cnt[base + 1];
    if (base + 2 < n) v2 = cnt[base + 2];
    if (base + 3 < n) v3 = cnt[base + 3];
    int tsum = v0 + v1 + v2 + v3;
    int x = tsum;
#pragma unroll
    for (int o = 1; o < 32; o <<= 1) {
        int y = __shfl_up_sync(0xffffffffu, x, o);
        if (lane >= o) x += y;
    }
    __shared__ int wsum[8];
    if (lane == 31) wsum[wid] = x;
    __syncthreads();
    if (t == 0) {
        int run = 0;
#pragma unroll
        for (int i = 0; i < 8; i++) { int tmp = wsum[i]; wsum[i] = run; run += tmp; }
    }
    __syncthreads();
    int excl = block_off + wsum[wid] + (x - tsum);
    if (base + 0 < n) off[base + 0] = excl; excl += v0;
    if (base + 1 < n) off[base + 1] = excl; excl += v1;
    if (base + 2 < n) off[base + 2] = excl; excl += v2;
    if (base + 3 < n) off[base + 3] = excl;
}

// Pure scatter, 2 edges of each hop per thread -> two independent
// atomic->store chains for latency hiding. Countdown leaves cnt at zero.
#define NHALF (NEDGE / 2)
__global__ void __launch_bounds__(256) scatter_kernel(
    const int* __restrict__ dsrc, const int* __restrict__ ddst,
    const float* __restrict__ dw,
    const int* __restrict__ usrc, const int* __restrict__ udst,
    const float* __restrict__ uw)
{
    int i = blockIdx.x * blockDim.x + threadIdx.x;     // 0 .. NHALF-1
    int i2 = i + NHALF;

    int da = ddst[i],  db = ddst[i2];
    int ua = udst[i],  ub = udst[i2];
    int sa = dsrc[i],  sb = dsrc[i2];
    int va = usrc[i],  vb = usrc[i2];
    float wa = dw[i],  wb = dw[i2];
    float xa = uw[i],  xb = uw[i2];

    int pa = atomicAdd(&g_cnt_down[da], -1);
    int pb = atomicAdd(&g_cnt_down[db], -1);
    int qa = atomicAdd(&g_cnt_up[ua], -1);
    int qb = atomicAdd(&g_cnt_up[ub], -1);

    g_edges_down[g_off_down[da] + pa - 1] = make_int2(sa, __float_as_int(wa));
    g_edges_down[g_off_down[db] + pb - 1] = make_int2(sb, __float_as_int(wb));
    g_edges_up[g_off_up[ua] + qa - 1]     = make_int2(va, __float_as_int(xa));
    g_edges_up[g_off_up[ub] + qb - 1]     = make_int2(vb, __float_as_int(xb));
}

// ---------------- gather-only projections ------------------------------------

__device__ __forceinline__ float4 h4_to_f4(uint2 p) {
    float2 a = __half22float2(*reinterpret_cast<__half2*>(&p.x));
    float2 b = __half22float2(*reinterpret_cast<__half2*>(&p.y));
    return make_float4(a.x, a.y, b.x, b.y);
}

__device__ __forceinline__ void accum1(float4& acc, float& sw, float w, float4 v) {
    sw += w;
    acc.x = fmaf(w, v.x, acc.x);
    acc.y = fmaf(w, v.y, acc.y);
    acc.z = fmaf(w, v.z, acc.z);
    acc.w = fmaf(w, v.w, acc.w);
}

// Best-known structure (round 7): per-lane uint2, warp-wide 256B row per
// gather, 4-edge unroll. Edge records streamed with __ldcs (single use).
__device__ __forceinline__ void segment_reduce4(
    const uint2* __restrict__ rows, const int2* __restrict__ edges,
    int beg, int end, int lane, float4& acc, float& sw)
{
    int e = beg;
    for (; e + 3 < end; e += 4) {
        int2 r0 = __ldcs(&edges[e]);
        int2 r1 = __ldcs(&edges[e + 1]);
        int2 r2 = __ldcs(&edges[e + 2]);
        int2 r3 = __ldcs(&edges[e + 3]);
        uint2 p0 = __ldg(&rows[(size_t)r0.x * (FEAT / 4) + lane]);
        uint2 p1 = __ldg(&rows[(size_t)r1.x * (FEAT / 4) + lane]);
        uint2 p2 = __ldg(&rows[(size_t)r2.x * (FEAT / 4) + lane]);
        uint2 p3 = __ldg(&rows[(size_t)r3.x * (FEAT / 4) + lane]);
        accum1(acc, sw, __int_as_float(r0.y), h4_to_f4(p0));
        accum1(acc, sw, __int_as_float(r1.y), h4_to_f4(p1));
        accum1(acc, sw, __int_as_float(r2.y), h4_to_f4(p2));
        accum1(acc, sw, __int_as_float(r3.y), h4_to_f4(p3));
    }
    for (; e < end; e++) {
        int2 r0 = __ldcs(&edges[e]);
        float4 v = h4_to_f4(__ldg(&rows[(size_t)r0.x * (FEAT / 4) + lane]));
        accum1(acc, sw, __int_as_float(r0.y), v);
    }
}

// Down: one warp per truncated row. fp16 gather, fp32 accumulate, fp16 store.
__global__ void __launch_bounds__(256) down_csr_kernel() {
    int g = (blockIdx.x * blockDim.x + threadIdx.x) >> 5;
    int lane = threadIdx.x & 31;
    if (g >= G_TRUNC) return;
    int beg = g_off_down[g];
    int end = g_off_down[g + 1];
    float4 acc = make_float4(0.f, 0.f, 0.f, 0.f);
    float sw = 0.f;
    segment_reduce4(reinterpret_cast<const uint2*>(g_xh),
                    g_edges_down, beg, end, lane, acc, sw);
    float inv = 1.f / fmaxf(sw, EPSV);
    __half2 h01 = __floats2half2_rn(acc.x * inv, acc.y * inv);
    __half2 h23 = __floats2half2_rn(acc.z * inv, acc.w * inv);
    reinterpret_cast<uint2*>(g_xc + (size_t)g * FEAT)[lane] =
        make_uint2(*reinterpret_cast<unsigned*>(&h01),
                   *reinterpret_cast<unsigned*>(&h23));
}

// Up: one warp per data row. fp16 gather of xc, fp32 accumulate, streaming store.
__global__ void __launch_bounds__(256) up_csr_kernel(float* __restrict__ out) {
    int g = (blockIdx.x * blockDim.x + threadIdx.x) >> 5;
    int lane = threadIdx.x & 31;
    if (g >= G_DATA) return;
    int beg = g_off_up[g];
    int end = g_off_up[g + 1];
    float4 acc = make_float4(0.f, 0.f, 0.f, 0.f);
    float sw = 0.f;
    segment_reduce4(reinterpret_cast<const uint2*>(g_xc),
                    g_edges_up, beg, end, lane, acc, sw);
    float inv = 1.f / fmaxf(sw, EPSV);
    __stcs(reinterpret_cast<float4*>(out + (size_t)g * FEAT) + lane,
           make_float4(acc.x * inv, acc.y * inv, acc.z * inv, acc.w * inv));
}

// ---------------- launch -----------------------------------------------------

extern "C" void kernel_launch(void* const* d_in, const int* in_sizes, int n_in,
                              void* d_out, int out_size) {
    const float* x        = (const float*)d_in[0];   // (1,2,1,G_DATA,FEAT)
    const int*   down_src = (const int*)  d_in[1];
    const int*   down_dst = (const int*)  d_in[2];
    const float* down_w   = (const float*)d_in[3];
    const int*   up_src   = (const int*)  d_in[4];
    const int*   up_dst   = (const int*)  d_in[5];
    const float* up_w     = (const float*)d_in[6];
    float* out = (float*)d_out;
    (void)in_sizes; (void)n_in; (void)out_size;

    // x[:, -1, ...] slice = second half along dim 1.
    const float* x_slice = x + (size_t)G_DATA * FEAT;

    // Fused histogram + fp16 convert (atomic work overlaps the DRAM stream).
    hist_convert_kernel<<<NEDGE / 4 / 256, 256>>>(down_dst, up_dst, x_slice);
    // Scans -> row offsets.
    scan_partial_both<<<NBLK_DOWN + NBLK_UP, 256>>>();
    scan_final_both<<<NBLK_DOWN + NBLK_UP, 256>>>();
    // Pure scatter with dual independent chains per thread.
    scatter_kernel<<<NHALF / 256, 256>>>(down_src, down_dst, down_w,
                                         up_src, up_dst, up_w);
    // Gather-only projections.
    down_csr_kernel<<<(G_TRUNC + 7) / 8, 256>>>();
    up_csr_kernel<<<G_DATA / 8, 256>>>(out);
}

// round 11
// speedup vs baseline: 1.3392x; 1.3392x over previous
#include <cuda_runtime.h>
#include <cuda_fp16.h>
#include <cstdint>

#define G_DATA  262144
#define G_TRUNC 40000
#define NEDGE   1048576
#define FEAT    128
#define EPSV    1e-8f

#define NBLK_DOWN 40     // ceil(G_TRUNC/1024)
#define NBLK_UP   256    // G_DATA/1024

// ---------------- scratch (__device__ globals; no allocation allowed) --------
// INVARIANT: g_cnt_* are zero at entry to kernel_launch. They start zero
// (static init) and the countdown scatter returns them to zero every call.
__device__ __half g_xh[(size_t)G_DATA * FEAT];        // 67 MB fp16 copy of x slice
__device__ __half g_xc[(size_t)G_TRUNC * FEAT];       // 10.2 MB fp16 intermediate
__device__ int   g_cnt_down[G_TRUNC];
__device__ int   g_cnt_up[G_DATA];
__device__ int   g_off_down[G_TRUNC + 1];
__device__ int   g_off_up[G_DATA + 1];
__device__ int   g_bsum_down[NBLK_DOWN];
__device__ int   g_bsum_up[NBLK_UP];
__device__ int2  g_edges_down[NEDGE];                 // (src, w bits) bucketed by dst
__device__ int2  g_edges_up[NEDGE];

// ---------------- CSR build --------------------------------------------------

__global__ void hist_kernel(const int* __restrict__ ddst, const int* __restrict__ udst) {
    int i = blockIdx.x * blockDim.x + threadIdx.x;
    if (i < NEDGE) {
        atomicAdd(&g_cnt_down[ddst[i]], 1);
        atomicAdd(&g_cnt_up[udst[i]], 1);
    }
}

// Per-1024-chunk sums for both arrays in one launch (blocks [0,40)=down).
__global__ void scan_partial_both() {
    __shared__ int red[256];
    int blk = blockIdx.x;
    const int* cnt; int* bsum; int n; int b;
    if (blk < NBLK_DOWN) { cnt = g_cnt_down; bsum = g_bsum_down; n = G_TRUNC; b = blk; }
    else                 { cnt = g_cnt_up;   bsum = g_bsum_up;   n = G_DATA;  b = blk - NBLK_DOWN; }
    int base = b * 1024 + threadIdx.x * 4;
    int s = 0;
#pragma unroll
    for (int j = 0; j < 4; j++) { int i = base + j; if (i < n) s += cnt[i]; }
    red[threadIdx.x] = s;
    __syncthreads();
    for (int off = 128; off > 0; off >>= 1) {
        if (threadIdx.x < off) red[threadIdx.x] += red[threadIdx.x + off];
        __syncthreads();
    }
    if (threadIdx.x == 0) bsum[b] = red[0];
}

// Per-element exclusive scan. Each block redundantly scans the (<=256) block
// sums itself. cnt is left intact (the scatter's countdown cursor consumes it).
__global__ void scan_final_both() {
    int blk = blockIdx.x;
    const int* cnt; int* off; const int* bsum; int n, nblk, b;
    if (blk < NBLK_DOWN) { cnt = g_cnt_down; off = g_off_down; bsum = g_bsum_down;
                           n = G_TRUNC; nblk = NBLK_DOWN; b = blk; }
    else                 { cnt = g_cnt_up;   off = g_off_up;   bsum = g_bsum_up;
                           n = G_DATA;  nblk = NBLK_UP;   b = blk - NBLK_DOWN; }
    int t = threadIdx.x;
    int lane = t & 31, wid = t >> 5;

    __shared__ int s[256];
    int bv = (t < nblk) ? bsum[t] : 0;
    s[t] = bv;
    __syncthreads();
    for (int o = 1; o < 256; o <<= 1) {
        int add = (t >= o) ? s[t - o] : 0;
        __syncthreads();
        s[t] += add;
        __syncthreads();
    }
    int block_off = (b > 0) ? s[b - 1] : 0;
    if (b == 0 && t == 0) off[n] = s[nblk - 1];   // grand total

    int base = b * 1024 + t * 4;
    int v0 = 0, v1 = 0, v2 = 0, v3 = 0;
    if (base + 0 < n) v0 = cnt[base + 0];
    if (base + 1 < n) v1 = cnt[base + 1];
    if (base + 2 < n) v2 = cnt[base + 2];
    if (base + 3 < n) v3 = cnt[base + 3];
    int tsum = v0 + v1 + v2 + v3;
    int x = tsum;
#pragma unroll
    for (int o = 1; o < 32; o <<= 1) {
        int y = __shfl_up_sync(0xffffffffu, x, o);
        if (lane >= o) x += y;
    }
    __shared__ int wsum[8];
    if (lane == 31) wsum[wid] = x;
    __syncthreads();
    if (t == 0) {
        int run = 0;
#pragma unroll
        for (int i = 0; i < 8; i++) { int tmp = wsum[i]; wsum[i] = run; run += tmp; }
    }
    __syncthreads();
    int excl = block_off + wsum[wid] + (x - tsum);
    if (base + 0 < n) off[base + 0] = excl; excl += v0;
    if (base + 1 < n) off[base + 1] = excl; excl += v1;
    if (base + 2 < n) off[base + 2] = excl; excl += v2;
    if (base + 3 < n) off[base + 3] = excl;
}

// Fused scatter + fp32->fp16 convert (round-7 structure: 1 edge/hop/thread).
// Convert's independent streaming loads are issued FIRST so they fill the
// memory pipe while the scatter's serial ldg->atomic->store chain drains.
// Countdown cursor leaves cnt at zero for the next replay.
__global__ void __launch_bounds__(256) scatter_convert_kernel(
    const int* __restrict__ dsrc, const int* __restrict__ ddst,
    const float* __restrict__ dw,
    const int* __restrict__ usrc, const int* __restrict__ udst,
    const float* __restrict__ uw,
    const float* __restrict__ x)
{
    int i = blockIdx.x * blockDim.x + threadIdx.x;

    // ---- convert: 8 independent float4 streams (8 * NEDGE == G_DATA*FEAT/4,
    // so no bounds check needed) ----
    const float4* x4 = reinterpret_cast<const float4*>(x);
    float4 v[8];
#pragma unroll
    for (int k = 0; k < 8; k++) v[k] = __ldcs(&x4[i + k * NEDGE]);

    // ---- scatter (edges -> dst-bucketed arrays) ----
    {
        int d = ddst[i];
        int idx = atomicAdd(&g_cnt_down[d], -1);
        g_edges_down[g_off_down[d] + idx - 1] = make_int2(dsrc[i], __float_as_int(dw[i]));
    }
    {
        int d = udst[i];
        int idx = atomicAdd(&g_cnt_up[d], -1);
        g_edges_up[g_off_up[d] + idx - 1] = make_int2(usrc[i], __float_as_int(uw[i]));
    }

    // ---- store converted fp16 ----
    uint2* xh2 = reinterpret_cast<uint2*>(g_xh);
#pragma unroll
    for (int k = 0; k < 8; k++) {
        __half2 h01 = __floats2half2_rn(v[k].x, v[k].y);
        __half2 h23 = __floats2half2_rn(v[k].z, v[k].w);
        xh2[i + k * NEDGE] = make_uint2(*reinterpret_cast<unsigned*>(&h01),
                                        *reinterpret_cast<unsigned*>(&h23));
    }
}

// ---------------- gather-only projections ------------------------------------

__device__ __forceinline__ float4 h4_to_f4(uint2 p) {
    float2 a = __half22float2(*reinterpret_cast<__half2*>(&p.x));
    float2 b = __half22float2(*reinterpret_cast<__half2*>(&p.y));
    return make_float4(a.x, a.y, b.x, b.y);
}

__device__ __forceinline__ void accum1(float4& acc, float& sw, float w, float4 v) {
    sw += w;
    acc.x = fmaf(w, v.x, acc.x);
    acc.y = fmaf(w, v.y, acc.y);
    acc.z = fmaf(w, v.z, acc.z);
    acc.w = fmaf(w, v.w, acc.w);
}

// Round-7 structure: per-lane uint2, warp-wide 256B row per gather, 4-edge
// unroll. Edge records streamed with __ldcs (single-use; keep xh/xc in L2).
__device__ __forceinline__ void segment_reduce4(
    const uint2* __restrict__ rows, const int2* __restrict__ edges,
    int beg, int end, int lane, float4& acc, float& sw)
{
    int e = beg;
    for (; e + 3 < end; e += 4) {
        int2 r0 = __ldcs(&edges[e]);
        int2 r1 = __ldcs(&edges[e + 1]);
        int2 r2 = __ldcs(&edges[e + 2]);
        int2 r3 = __ldcs(&edges[e + 3]);
        uint2 p0 = __ldg(&rows[(size_t)r0.x * (FEAT / 4) + lane]);
        uint2 p1 = __ldg(&rows[(size_t)r1.x * (FEAT / 4) + lane]);
        uint2 p2 = __ldg(&rows[(size_t)r2.x * (FEAT / 4) + lane]);
        uint2 p3 = __ldg(&rows[(size_t)r3.x * (FEAT / 4) + lane]);
        accum1(acc, sw, __int_as_float(r0.y), h4_to_f4(p0));
        accum1(acc, sw, __int_as_float(r1.y), h4_to_f4(p1));
        accum1(acc, sw, __int_as_float(r2.y), h4_to_f4(p2));
        accum1(acc, sw, __int_as_float(r3.y), h4_to_f4(p3));
    }
    for (; e < end; e++) {
        int2 r0 = __ldcs(&edges[e]);
        float4 v = h4_to_f4(__ldg(&rows[(size_t)r0.x * (FEAT / 4) + lane]));
        accum1(acc, sw, __int_as_float(r0.y), v);
    }
}

// Down: one warp per truncated row. fp16 gather, fp32 accumulate, fp16 store.
__global__ void __launch_bounds__(256) down_csr_kernel() {
    int g = (blockIdx.x * blockDim.x + threadIdx.x) >> 5;
    int lane = threadIdx.x & 31;
    if (g >= G_TRUNC) return;
    int beg = g_off_down[g];
    int end = g_off_down[g + 1];
    float4 acc = make_float4(0.f, 0.f, 0.f, 0.f);
    float sw = 0.f;
    segment_reduce4(reinterpret_cast<const uint2*>(g_xh),
                    g_edges_down, beg, end, lane, acc, sw);
    float inv = 1.f / fmaxf(sw, EPSV);
    __half2 h01 = __floats2half2_rn(acc.x * inv, acc.y * inv);
    __half2 h23 = __floats2half2_rn(acc.z * inv, acc.w * inv);
    reinterpret_cast<uint2*>(g_xc + (size_t)g * FEAT)[lane] =
        make_uint2(*reinterpret_cast<unsigned*>(&h01),
                   *reinterpret_cast<unsigned*>(&h23));
}

// Up: one warp per data row. fp16 gather of xc, fp32 accumulate, streaming store.
__global__ void __launch_bounds__(256) up_csr_kernel(float* __restrict__ out) {
    int g = (blockIdx.x * blockDim.x + threadIdx.x) >> 5;
    int lane = threadIdx.x & 31;
    if (g >= G_DATA) return;
    int beg = g_off_up[g];
    int end = g_off_up[g + 1];
    float4 acc = make_float4(0.f, 0.f, 0.f, 0.f);
    float sw = 0.f;
    segment_reduce4(reinterpret_cast<const uint2*>(g_xc),
                    g_edges_up, beg, end, lane, acc, sw);
    float inv = 1.f / fmaxf(sw, EPSV);
    __stcs(reinterpret_cast<float4*>(out + (size_t)g * FEAT) + lane,
           make_float4(acc.x * inv, acc.y * inv, acc.z * inv, acc.w * inv));
}

// ---------------- launch -----------------------------------------------------

extern "C" void kernel_launch(void* const* d_in, const int* in_sizes, int n_in,
                              void* d_out, int out_size) {
    const float* x        = (const float*)d_in[0];   // (1,2,1,G_DATA,FEAT)
    const int*   down_src = (const int*)  d_in[1];
    const int*   down_dst = (const int*)  d_in[2];
    const float* down_w   = (const float*)d_in[3];
    const int*   up_src   = (const int*)  d_in[4];
    const int*   up_dst   = (const int*)  d_in[5];
    const float* up_w     = (const float*)d_in[6];
    float* out = (float*)d_out;
    (void)in_sizes; (void)n_in; (void)out_size;

    // x[:, -1, ...] slice = second half along dim 1.
    const float* x_slice = x + (size_t)G_DATA * FEAT;

    // CSR build (counters are zero at entry — countdown invariant)
    hist_kernel<<<NEDGE / 256, 256>>>(down_dst, up_dst);
    scan_partial_both<<<NBLK_DOWN + NBLK_UP, 256>>>();
    scan_final_both<<<NBLK_DOWN + NBLK_UP, 256>>>();
    // Fused scatter + convert immediately before down (xh stays L2-hot).
    scatter_convert_kernel<<<NEDGE / 256, 256>>>(down_src, down_dst, down_w,
                                                 up_src, up_dst, up_w, x_slice);
    // Gather-only projections.
    down_csr_kernel<<<(G_TRUNC + 7) / 8, 256>>>();
    up_csr_kernel<<<G_DATA / 8, 256>>>(out);
}

// round 12
// speedup vs baseline: 1.3938x; 1.0408x over previous
#include <cuda_runtime.h>
#include <cuda_fp16.h>
#include <cstdint>

#define G_DATA  262144
#define G_TRUNC 40000
#define NEDGE   1048576
#define FEAT    128
#define EPSV    1e-8f

#define NBLK_DOWN 40     // ceil(G_TRUNC/1024)
#define NBLK_UP   256    // G_DATA/1024

// ---------------- scratch (__device__ globals; no allocation allowed) --------
// INVARIANT: g_cnt_* are zero at entry to kernel_launch. They start zero
// (static init) and the countdown scatter returns them to zero every call.
__device__ __half g_xh[(size_t)G_DATA * FEAT];        // 67 MB fp16 copy of x slice
__device__ __half g_xc[(size_t)G_TRUNC * FEAT];       // 10.2 MB fp16 intermediate
__device__ int   g_cnt_down[G_TRUNC];
__device__ int   g_cnt_up[G_DATA];
__device__ int   g_off_down[G_TRUNC + 1];
__device__ int   g_off_up[G_DATA + 1];
__device__ int   g_bsum_down[NBLK_DOWN];
__device__ int   g_bsum_up[NBLK_UP];
__device__ int2  g_edges_down[NEDGE];                 // (src, w bits) bucketed by dst
__device__ int2  g_edges_up[NEDGE];

// ---------------- CSR build --------------------------------------------------

__global__ void hist_kernel(const int* __restrict__ ddst, const int* __restrict__ udst) {
    int i = blockIdx.x * blockDim.x + threadIdx.x;
    if (i < NEDGE) {
        atomicAdd(&g_cnt_down[ddst[i]], 1);
        atomicAdd(&g_cnt_up[udst[i]], 1);
    }
}

// Per-1024-chunk sums for both arrays in one launch (blocks [0,40)=down).
__global__ void scan_partial_both() {
    __shared__ int red[256];
    int blk = blockIdx.x;
    const int* cnt; int* bsum; int n; int b;
    if (blk < NBLK_DOWN) { cnt = g_cnt_down; bsum = g_bsum_down; n = G_TRUNC; b = blk; }
    else                 { cnt = g_cnt_up;   bsum = g_bsum_up;   n = G_DATA;  b = blk - NBLK_DOWN; }
    int base = b * 1024 + threadIdx.x * 4;
    int s = 0;
#pragma unroll
    for (int j = 0; j < 4; j++) { int i = base + j; if (i < n) s += cnt[i]; }
    red[threadIdx.x] = s;
    __syncthreads();
    for (int off = 128; off > 0; off >>= 1) {
        if (threadIdx.x < off) red[threadIdx.x] += red[threadIdx.x + off];
        __syncthreads();
    }
    if (threadIdx.x == 0) bsum[b] = red[0];
}

// Per-element exclusive scan. Each block redundantly scans the (<=256) block
// sums itself. cnt is left intact (the scatter's countdown cursor consumes it).
__global__ void scan_final_both() {
    int blk = blockIdx.x;
    const int* cnt; int* off; const int* bsum; int n, nblk, b;
    if (blk < NBLK_DOWN) { cnt = g_cnt_down; off = g_off_down; bsum = g_bsum_down;
                           n = G_TRUNC; nblk = NBLK_DOWN; b = blk; }
    else                 { cnt = g_cnt_up;   off = g_off_up;   bsum = g_bsum_up;
                           n = G_DATA;  nblk = NBLK_UP;   b = blk - NBLK_DOWN; }
    int t = threadIdx.x;
    int lane = t & 31, wid = t >> 5;

    __shared__ int s[256];
    int bv = (t < nblk) ? bsum[t] : 0;
    s[t] = bv;
    __syncthreads();
    for (int o = 1; o < 256; o <<= 1) {
        int add = (t >= o) ? s[t - o] : 0;
        __syncthreads();
        s[t] += add;
        __syncthreads();
    }
    int block_off = (b > 0) ? s[b - 1] : 0;
    if (b == 0 && t == 0) off[n] = s[nblk - 1];   // grand total

    int base = b * 1024 + t * 4;
    int v0 = 0, v1 = 0, v2 = 0, v3 = 0;
    if (base + 0 < n) v0 = cnt[base + 0];
    if (base + 1 < n) v1 = cnt[base + 1];
    if (base + 2 < n) v2 = cnt[base + 2];
    if (base + 3 < n) v3 = cnt[base + 3];
    int tsum = v0 + v1 + v2 + v3;
    int x = tsum;
#pragma unroll
    for (int o = 1; o < 32; o <<= 1) {
        int y = __shfl_up_sync(0xffffffffu, x, o);
        if (lane >= o) x += y;
    }
    __shared__ int wsum[8];
    if (lane == 31) wsum[wid] = x;
    __syncthreads();
    if (t == 0) {
        int run = 0;
#pragma unroll
        for (int i = 0; i < 8; i++) { int tmp = wsum[i]; wsum[i] = run; run += tmp; }
    }
    __syncthreads();
    int excl = block_off + wsum[wid] + (x - tsum);
    if (base + 0 < n) off[base + 0] = excl; excl += v0;
    if (base + 1 < n) off[base + 1] = excl; excl += v1;
    if (base + 2 < n) off[base + 2] = excl; excl += v2;
    if (base + 3 < n) off[base + 3] = excl;
}

// Fused scatter + fp32->fp16 convert. Convert's 8 independent streaming
// loads are front-batched (measured -2.1us vs convert-after-scatter); the
// reg cost (48) / occ drop (53%) is contained to this kernel and paid for.
// Countdown cursor leaves cnt at zero for the next replay.
__global__ void __launch_bounds__(256) scatter_convert_kernel(
    const int* __restrict__ dsrc, const int* __restrict__ ddst,
    const float* __restrict__ dw,
    const int* __restrict__ usrc, const int* __restrict__ udst,
    const float* __restrict__ uw,
    const float* __restrict__ x)
{
    int i = blockIdx.x * blockDim.x + threadIdx.x;

    // ---- convert loads: 8 independent float4 streams
    // (8 * NEDGE == G_DATA*FEAT/4 exactly; no bounds check) ----
    const float4* x4 = reinterpret_cast<const float4*>(x);
    float4 v[8];
#pragma unroll
    for (int k = 0; k < 8; k++) v[k] = __ldcs(&x4[i + k * NEDGE]);

    // ---- scatter (edges -> dst-bucketed arrays) ----
    {
        int d = ddst[i];
        int idx = atomicAdd(&g_cnt_down[d], -1);
        g_edges_down[g_off_down[d] + idx - 1] = make_int2(dsrc[i], __float_as_int(dw[i]));
    }
    {
        int d = udst[i];
        int idx = atomicAdd(&g_cnt_up[d], -1);
        g_edges_up[g_off_up[d] + idx - 1] = make_int2(usrc[i], __float_as_int(uw[i]));
    }

    // ---- store converted fp16 ----
    uint2* xh2 = reinterpret_cast<uint2*>(g_xh);
#pragma unroll
    for (int k = 0; k < 8; k++) {
        __half2 h01 = __floats2half2_rn(v[k].x, v[k].y);
        __half2 h23 = __floats2half2_rn(v[k].z, v[k].w);
        xh2[i + k * NEDGE] = make_uint2(*reinterpret_cast<unsigned*>(&h01),
                                        *reinterpret_cast<unsigned*>(&h23));
    }
}

// ---------------- gather-only projections ------------------------------------

__device__ __forceinline__ float4 h4_to_f4(uint2 p) {
    float2 a = __half22float2(*reinterpret_cast<__half2*>(&p.x));
    float2 b = __half22float2(*reinterpret_cast<__half2*>(&p.y));
    return make_float4(a.x, a.y, b.x, b.y);
}

__device__ __forceinline__ void accum1(float4& acc, float& sw, float w, float4 v) {
    sw += w;
    acc.x = fmaf(w, v.x, acc.x);
    acc.y = fmaf(w, v.y, acc.y);
    acc.z = fmaf(w, v.z, acc.z);
    acc.w = fmaf(w, v.w, acc.w);
}

// Round-7 structure exactly: per-lane uint2, warp-wide 256B row per gather,
// 4-edge unroll. Edge records via plain __ldg — they're warp-uniform
// broadcast reads walking a 128B line sequentially; default caching lets one
// L1 line serve 16 edges (measured: __ldcs here cost +8.5us).
__device__ __forceinline__ void segment_reduce4(
    const uint2* __restrict__ rows, const int2* __restrict__ edges,
    int beg, int end, int lane, float4& acc, float& sw)
{
    int e = beg;
    for (; e + 3 < end; e += 4) {
        int2 r0 = __ldg(&edges[e]);
        int2 r1 = __ldg(&edges[e + 1]);
        int2 r2 = __ldg(&edges[e + 2]);
        int2 r3 = __ldg(&edges[e + 3]);
        uint2 p0 = __ldg(&rows[(size_t)r0.x * (FEAT / 4) + lane]);
        uint2 p1 = __ldg(&rows[(size_t)r1.x * (FEAT / 4) + lane]);
        uint2 p2 = __ldg(&rows[(size_t)r2.x * (FEAT / 4) + lane]);
        uint2 p3 = __ldg(&rows[(size_t)r3.x * (FEAT / 4) + lane]);
        accum1(acc, sw, __int_as_float(r0.y), h4_to_f4(p0));
        accum1(acc, sw, __int_as_float(r1.y), h4_to_f4(p1));
        accum1(acc, sw, __int_as_float(r2.y), h4_to_f4(p2));
        accum1(acc, sw, __int_as_float(r3.y), h4_to_f4(p3));
    }
    for (; e < end; e++) {
        int2 r0 = __ldg(&edges[e]);
        float4 v = h4_to_f4(__ldg(&rows[(size_t)r0.x * (FEAT / 4) + lane]));
        accum1(acc, sw, __int_as_float(r0.y), v);
    }
}

// Down: one warp per truncated row. fp16 gather, fp32 accumulate, fp16 store.
__global__ void __launch_bounds__(256) down_csr_kernel() {
    int g = (blockIdx.x * blockDim.x + threadIdx.x) >> 5;
    int lane = threadIdx.x & 31;
    if (g >= G_TRUNC) return;
    int beg = g_off_down[g];
    int end = g_off_down[g + 1];
    float4 acc = make_float4(0.f, 0.f, 0.f, 0.f);
    float sw = 0.f;
    segment_reduce4(reinterpret_cast<const uint2*>(g_xh),
                    g_edges_down, beg, end, lane, acc, sw);
    float inv = 1.f / fmaxf(sw, EPSV);
    __half2 h01 = __floats2half2_rn(acc.x * inv, acc.y * inv);
    __half2 h23 = __floats2half2_rn(acc.z * inv, acc.w * inv);
    reinterpret_cast<uint2*>(g_xc + (size_t)g * FEAT)[lane] =
        make_uint2(*reinterpret_cast<unsigned*>(&h01),
                   *reinterpret_cast<unsigned*>(&h23));
}

// Up: one warp per data row. fp16 gather of xc, fp32 accumulate, streaming store.
__global__ void __launch_bounds__(256) up_csr_kernel(float* __restrict__ out) {
    int g = (blockIdx.x * blockDim.x + threadIdx.x) >> 5;
    int lane = threadIdx.x & 31;
    if (g >= G_DATA) return;
    int beg = g_off_up[g];
    int end = g_off_up[g + 1];
    float4 acc = make_float4(0.f, 0.f, 0.f, 0.f);
    float sw = 0.f;
    segment_reduce4(reinterpret_cast<const uint2*>(g_xc),
                    g_edges_up, beg, end, lane, acc, sw);
    float inv = 1.f / fmaxf(sw, EPSV);
    __stcs(reinterpret_cast<float4*>(out + (size_t)g * FEAT) + lane,
           make_float4(acc.x * inv, acc.y * inv, acc.z * inv, acc.w * inv));
}

// ---------------- launch -----------------------------------------------------

extern "C" void kernel_launch(void* const* d_in, const int* in_sizes, int n_in,
                              void* d_out, int out_size) {
    const float* x        = (const float*)d_in[0];   // (1,2,1,G_DATA,FEAT)
    const int*   down_src = (const int*)  d_in[1];
    const int*   down_dst = (const int*)  d_in[2];
    const float* down_w   = (const float*)d_in[3];
    const int*   up_src   = (const int*)  d_in[4];
    const int*   up_dst   = (const int*)  d_in[5];
    const float* up_w     = (const float*)d_in[6];
    float* out = (float*)d_out;
    (void)in_sizes; (void)n_in; (void)out_size;

    // x[:, -1, ...] slice = second half along dim 1.
    const float* x_slice = x + (size_t)G_DATA * FEAT;

    // CSR build (counters are zero at entry — countdown invariant)
    hist_kernel<<<NEDGE / 256, 256>>>(down_dst, up_dst);
    scan_partial_both<<<NBLK_DOWN + NBLK_UP, 256>>>();
    scan_final_both<<<NBLK_DOWN + NBLK_UP, 256>>>();
    // Fused scatter + convert immediately before down (xh stays L2-hot).
    scatter_convert_kernel<<<NEDGE / 256, 256>>>(down_src, down_dst, down_w,
                                                 up_src, up_dst, up_w, x_slice);
    // Gather-only projections.
    down_csr_kernel<<<(G_TRUNC + 7) / 8, 256>>>();
    up_csr_kernel<<<G_DATA / 8, 256>>>(out);
}